// round 10
// baseline (speedup 1.0000x reference)
#include <cuda_runtime.h>
#include <cuda_bf16.h>
#include <cstdint>

// ICPMatcher: exact NN via compact counting-sorted 32^3 grid, 2 launches.
//
//   k_pre (ONE CTA, 1024 thr, 128KB dynamic smem = all cell counters):
//     zero -> count (smem atomics) -> exclusive scan (32 cells/thread +
//     shfl block scan) -> scatter to compact g_sortedTgt + g_cellStart.
//   k_nn (warp per source): r=1 scans the 3x3x3 cube as 9 CONTIGUOUS point
//     spans, lane-strided over points (balanced + coalesced). Shells r>=2
//     cell-based, prune ((r-1)h)^2 > bestD2 + margin.
//
// Exactness: identical cell coverage, identical fma distance chain, and
// order-independent packed (monotone(d')|idx) u64-min tie-break -> decisions
// bit-identical to all passing rounds.

typedef unsigned long long ull;

#define N_MAX   16384
#define G       32
#define NCELLS  (G * G * G)          // 32768
#define BBOX    6.0f
#define CELLH   0.375f
#define INVH    2.6666667f

static __device__ int    g_cellStart[NCELLS + 1];
static __device__ float4 g_sortedTgt[N_MAX];   // (x,y,z, bitcast(origIdx))

static __device__ __forceinline__ unsigned int map_f32(float f) {
    unsigned int b = __float_as_uint(f);
    return (b & 0x80000000u) ? ~b : (b | 0x80000000u);
}
static __device__ __forceinline__ float unmap_f32(unsigned int m) {
    return __uint_as_float((m & 0x80000000u) ? (m ^ 0x80000000u) : ~m);
}
static __device__ __forceinline__ int clampi(int v, int lo, int hi) {
    return v < lo ? lo : (v > hi ? hi : v);
}
static __device__ __forceinline__ void cellOf(float x, float y, float z,
                                              int& cx, int& cy, int& cz) {
    cx = clampi((int)floorf((x + BBOX) * INVH), 0, G - 1);
    cy = clampi((int)floorf((y + BBOX) * INVH), 0, G - 1);
    cz = clampi((int)floorf((z + BBOX) * INVH), 0, G - 1);
}

// ---- fused preprocessing: one CTA, all phases ------------------------------

__global__ __launch_bounds__(1024) void k_pre(const float* __restrict__ tgt,
                                              int n2) {
    extern __shared__ int sh[];          // NCELLS counters / cursors
    __shared__ int wsum[32];
    const int t = threadIdx.x;
    const int lane = t & 31;
    const int wid = t >> 5;

    // zero
    for (int c = t; c < NCELLS; c += 1024) sh[c] = 0;
    __syncthreads();

    // count
    for (int i = t; i < n2; i += 1024) {
        int cx, cy, cz;
        cellOf(tgt[3 * i], tgt[3 * i + 1], tgt[3 * i + 2], cx, cy, cz);
        atomicAdd(&sh[(cz * G + cy) * G + cx], 1);
    }
    __syncthreads();

    // exclusive scan: thread t owns cells [t*32, t*32+32)
    const int base_c = t * 32;
    int sum = 0;
#pragma unroll
    for (int k = 0; k < 32; k++) sum += sh[base_c + k];

    int s = sum;
#pragma unroll
    for (int off = 1; off < 32; off <<= 1) {
        int o = __shfl_up_sync(0xFFFFFFFFu, s, off);
        if (lane >= off) s += o;
    }
    if (lane == 31) wsum[wid] = s;
    __syncthreads();
    if (wid == 0) {
        int ws = wsum[lane];
#pragma unroll
        for (int off = 1; off < 32; off <<= 1) {
            int o = __shfl_up_sync(0xFFFFFFFFu, ws, off);
            if (lane >= off) ws += o;
        }
        wsum[lane] = ws;
    }
    __syncthreads();
    int run = s - sum + (wid > 0 ? wsum[wid - 1] : 0);  // exclusive prefix

#pragma unroll
    for (int k = 0; k < 32; k++) {
        const int v = sh[base_c + k];
        sh[base_c + k] = run;
        g_cellStart[base_c + k] = run;
        run += v;
    }
    if (t == 0) g_cellStart[NCELLS] = n2;
    __syncthreads();

    // scatter (sh[] now holds running cursors)
    for (int i = t; i < n2; i += 1024) {
        const float x = tgt[3 * i], y = tgt[3 * i + 1], z = tgt[3 * i + 2];
        int cx, cy, cz;
        cellOf(x, y, z, cx, cy, cz);
        const int pos = atomicAdd(&sh[(cz * G + cy) * G + cx], 1);
        g_sortedTgt[pos] = make_float4(x, y, z, __int_as_float(i));
    }
}

// ---- warp-cooperative NN search --------------------------------------------

__global__ __launch_bounds__(256) void k_nn(const float* __restrict__ src,
                                            float* __restrict__ out,
                                            int n1, int out_size) {
    const int warp = (blockIdx.x * blockDim.x + threadIdx.x) >> 5;
    const int lane = threadIdx.x & 31;
    if (warp >= n1) return;
    const int i = warp;

    const float x = src[3 * i], y = src[3 * i + 1], z = src[3 * i + 2];
    const float m2x = -2.f * x, m2y = -2.f * y, m2z = -2.f * z;
    const float s2 = fmaf(x, x, fmaf(y, y, z * z));

    int cx, cy, cz;
    cellOf(x, y, z, cx, cy, cz);

    ull best = 0xFFFFFFFFFFFFFFFFull;
    float bestD2 = __int_as_float(0x7f800000);

    // ---- r<=1: 3x3x3 cube as 9 contiguous point spans, lane-strided --------
    {
        const int x0 = max(cx - 1, 0), x1 = min(cx + 1, G - 1);
        ull lbest = best;
#pragma unroll
        for (int row = 0; row < 9; row++) {
            const int zz = cz + row / 3 - 1;
            const int yy = cy + row % 3 - 1;
            if (zz < 0 || zz >= G || yy < 0 || yy >= G) continue;
            const int cbase = (zz * G + yy) * G;
            const int p0 = __ldg(&g_cellStart[cbase + x0]);
            const int p1 = __ldg(&g_cellStart[cbase + x1 + 1]);
            for (int p = p0 + lane; p < p1; p += 32) {
                const float4 T = __ldg(&g_sortedTgt[p]);
                float t2 = fmaf(T.x, T.x, fmaf(T.y, T.y, T.z * T.z));
                float d  = fmaf(m2x, T.x, fmaf(m2y, T.y, fmaf(m2z, T.z, t2)));
                ull pk = ((ull)map_f32(d) << 32) |
                         (unsigned int)__float_as_int(T.w);
                if (pk < lbest) lbest = pk;
            }
        }
#pragma unroll
        for (int off = 16; off > 0; off >>= 1) {
            ull o = __shfl_xor_sync(0xFFFFFFFFu, lbest, off);
            if (o < lbest) lbest = o;
        }
        best = lbest;
        if (best != 0xFFFFFFFFFFFFFFFFull)
            bestD2 = unmap_f32((unsigned int)(best >> 32)) + s2;
    }

    // ---- r>=2 shells, cell-based (rare) ------------------------------------
    for (int r = 2; r <= G; r++) {
        const float lb = (float)(r - 1) * CELLH;
        if (lb * lb > bestD2 + 1e-3f) break;

        const int side = 2 * r + 1;
        const int area = side * side;
        const int ncub = side * area;

        ull lbest = best;
        for (int t = lane; t < ncub; t += 32) {
            const int dz = t / area - r;
            const int rm = t % area;
            const int dy = rm / side - r;
            const int dx = rm % side - r;
            const int ch = max(abs(dx), max(abs(dy), abs(dz)));
            if (ch < r) continue;                // interior already scanned
            const int xx = cx + dx, yy = cy + dy, zz = cz + dz;
            if (xx < 0 || xx >= G || yy < 0 || yy >= G || zz < 0 || zz >= G)
                continue;
            const int c = (zz * G + yy) * G + xx;
            const int p0 = __ldg(&g_cellStart[c]);
            const int p1 = __ldg(&g_cellStart[c + 1]);
            for (int p = p0; p < p1; p++) {
                const float4 T = __ldg(&g_sortedTgt[p]);
                float t2 = fmaf(T.x, T.x, fmaf(T.y, T.y, T.z * T.z));
                float d  = fmaf(m2x, T.x, fmaf(m2y, T.y, fmaf(m2z, T.z, t2)));
                ull pk = ((ull)map_f32(d) << 32) |
                         (unsigned int)__float_as_int(T.w);
                if (pk < lbest) lbest = pk;
            }
        }
#pragma unroll
        for (int off = 16; off > 0; off >>= 1) {
            ull o = __shfl_xor_sync(0xFFFFFFFFu, lbest, off);
            if (o < lbest) lbest = o;
        }
        best = lbest;
        bestD2 = unmap_f32((unsigned int)(best >> 32)) + s2;
    }

    if (lane == 0) {
        const float dist = unmap_f32((unsigned int)(best >> 32)) + s2;
        const unsigned int idx = (unsigned int)(best & 0xFFFFFFFFu);
        if (i < out_size) out[i] = dist;
        if (n1 + i < out_size) out[n1 + i] = (float)idx;
    }
}

// ---- launch ----------------------------------------------------------------

extern "C" void kernel_launch(void* const* d_in, const int* in_sizes, int n_in,
                              void* d_out, int out_size) {
    const float* src = (const float*)d_in[0];
    const float* tgt = (const float*)d_in[1];
    const int n1 = in_sizes[0] / 3;
    const int n2 = in_sizes[1] / 3;
    float* out = (float*)d_out;

    static bool attr_set = false;
    if (!attr_set) {
        cudaFuncSetAttribute(k_pre, cudaFuncAttributeMaxDynamicSharedMemorySize,
                             NCELLS * (int)sizeof(int));
        attr_set = true;
    }

    k_pre<<<1, 1024, NCELLS * sizeof(int)>>>(tgt, n2);

    const int warps_per_cta = 256 / 32;
    k_nn<<<(n1 + warps_per_cta - 1) / warps_per_cta, 256>>>(src, out, n1, out_size);
}